// round 4
// baseline (speedup 1.0000x reference)
#include <cuda_runtime.h>
#include <float.h>
#include <math.h>

#define B_ 8
#define C_ 32
#define H_ 512
#define W_ 512
#define HW_ (H_*W_)

typedef unsigned long long u64;

// Scratch (allocation-free rule: static __device__ arrays)
__device__ float g_fs[B_*C_*H_*W_];   // conv1x1 output (pre-attention)
__device__ float g_cm[B_*H_*W_];      // channel max plane
__device__ float g_ca[B_*H_*W_];      // channel mean plane

__device__ __forceinline__ float fsigmoid(float z) {
    return 1.0f / (1.0f + __expf(-z));
}

// ---- packed f32x2 helpers (sm_10x) ----
__device__ __forceinline__ u64 pack2(float lo, float hi) {
    u64 r; asm("mov.b64 %0, {%1,%2};" : "=l"(r) : "f"(lo), "f"(hi)); return r;
}
__device__ __forceinline__ u64 dup2(float v) { return pack2(v, v); }
__device__ __forceinline__ void unpack2(u64 v, float &lo, float &hi) {
    asm("mov.b64 {%0,%1}, %2;" : "=f"(lo), "=f"(hi) : "l"(v));
}
__device__ __forceinline__ u64 fma2(u64 a, u64 b, u64 c) {
    u64 d; asm("fma.rn.f32x2 %0, %1, %2, %3;" : "=l"(d) : "l"(a), "l"(b), "l"(c)); return d;
}
__device__ __forceinline__ u64 add2(u64 a, u64 b) {
    u64 d; asm("add.rn.f32x2 %0, %1, %2;" : "=l"(d) : "l"(a), "l"(b)); return d;
}

// ---------------------------------------------------------------------------
// Kernel A: per 2x2 patch — patch max/avg -> gate -> fused (concat + 1x1 conv)
// out[o] = sum_c x[c]*(gate[c]*w1[o,c] + w2[o,c]) + b[o]
// 4 threads per patch; each owns 8 output channels (low regs -> high occ).
// Accumulators are f32x2 over the horizontal pixel pair of the patch.
// Block 256 = 4 groups x 64 patches. Grid = (4, 256, 8).
// ---------------------------------------------------------------------------
__global__ __launch_bounds__(256, 3)
void kernelA(const float* __restrict__ x,
             const float* __restrict__ mlp_w,
             const float* __restrict__ mlp_b,
             const float* __restrict__ conv_w,
             const float* __restrict__ conv_b)
{
    __shared__ __align__(16) u64 s_w1d[32][32];   // [c][o] = dup(conv_w[o, c])
    __shared__ __align__(16) u64 s_w2d[32][32];   // [c][o] = dup(conv_w[o, 32+c])
    __shared__ __align__(16) u64 s_bd[32];
    __shared__ float2 s_red[4][64][4];            // per-group partial (mx, sum)

    const int tid = threadIdx.x;
    for (int i = tid; i < 1024; i += 256) {
        int o = i & 31, c = i >> 5;
        s_w1d[c][o] = dup2(conv_w[o * 64 + c]);
        s_w2d[c][o] = dup2(conv_w[o * 64 + 32 + c]);
    }
    if (tid < 32) s_bd[tid] = dup2(conv_b[tid]);
    __syncthreads();

    const int g  = tid >> 6;           // channel group: channels g*8 .. g*8+7
    const int p  = tid & 63;           // patch index within block
    const int wp = blockIdx.x * 64 + p;
    const int hp = blockIdx.y;
    const int b  = blockIdx.z;
    const int o0 = g * 8;

    const u64* __restrict__ x2 = (const u64*)x;
    const float mw  = __ldg(mlp_w);
    const float mb2 = 2.0f * __ldg(mlp_b);

    u64 acc[8][2];   // [local channel][0=top row pair, 1=bottom row pair]
#pragma unroll
    for (int k = 0; k < 8; k++) { acc[k][0] = 0ull; acc[k][1] = 0ull; }

#pragma unroll 4
    for (int c = 0; c < 32; c++) {
        unsigned pp = (((unsigned)(b * 32 + c)) * 512u + 2u * hp) * 256u + wp;
        u64 r0 = x2[pp];
        u64 r1 = x2[pp + 256];
        float r0x, r0y, r1x, r1y;
        unpack2(r0, r0x, r0y);
        unpack2(r1, r1x, r1y);
        float m = fmaxf(fmaxf(r0x, r0y), fmaxf(r1x, r1y));
        float a = 0.25f * ((r0x + r0y) + (r1x + r1y));
        float gt = fsigmoid(fmaf(m + a, mw, mb2));
        u64 gg = dup2(gt);
        const ulonglong2* __restrict__ w1p = (const ulonglong2*)&s_w1d[c][o0];
        const ulonglong2* __restrict__ w2p = (const ulonglong2*)&s_w2d[c][o0];
#pragma unroll
        for (int k2 = 0; k2 < 4; k2++) {
            ulonglong2 a1 = w1p[k2];
            ulonglong2 a2 = w2p[k2];
            u64 we0 = fma2(gg, a1.x, a2.x);
            u64 we1 = fma2(gg, a1.y, a2.y);
            acc[2*k2  ][0] = fma2(r0, we0, acc[2*k2  ][0]);
            acc[2*k2  ][1] = fma2(r1, we0, acc[2*k2  ][1]);
            acc[2*k2+1][0] = fma2(r0, we1, acc[2*k2+1][0]);
            acc[2*k2+1][1] = fma2(r1, we1, acc[2*k2+1][1]);
        }
    }

    // bias add
#pragma unroll
    for (int k = 0; k < 8; k++) {
        u64 bk = s_bd[o0 + k];
        acc[k][0] = add2(acc[k][0], bk);
        acc[k][1] = add2(acc[k][1], bk);
    }

    // partial channel max/sum over this group's 8 channels
    float mx[4], sm[4];
#pragma unroll
    for (int j = 0; j < 4; j++) { mx[j] = -FLT_MAX; sm[j] = 0.f; }
#pragma unroll
    for (int k = 0; k < 8; k++) {
        float lo, hi;
        unpack2(acc[k][0], lo, hi);
        mx[0] = fmaxf(mx[0], lo); sm[0] += lo;
        mx[1] = fmaxf(mx[1], hi); sm[1] += hi;
        unpack2(acc[k][1], lo, hi);
        mx[2] = fmaxf(mx[2], lo); sm[2] += lo;
        mx[3] = fmaxf(mx[3], hi); sm[3] += hi;
    }
#pragma unroll
    for (int j = 0; j < 4; j++) s_red[g][p][j] = make_float2(mx[j], sm[j]);

    // fs stores: u64 adjacent-pixel pairs, coalesced (lanes = consecutive p)
    u64* __restrict__ fs2 = (u64*)g_fs;
#pragma unroll
    for (int k = 0; k < 8; k++) {
        int o = o0 + k;
        unsigned pp = (((unsigned)(b * 32 + o)) * 512u + 2u * hp) * 256u + wp;
        fs2[pp]       = acc[k][0];
        fs2[pp + 256] = acc[k][1];
    }

    __syncthreads();
    if (g == 0) {
#pragma unroll
        for (int j = 0; j < 4; j++) {
            float2 r1s = s_red[1][p][j];
            float2 r2s = s_red[2][p][j];
            float2 r3s = s_red[3][p][j];
            mx[j] = fmaxf(fmaxf(mx[j], r1s.x), fmaxf(r2s.x, r3s.x));
            sm[j] = (sm[j] + r1s.y + r2s.y + r3s.y) * (1.0f / 32.0f);
        }
        unsigned q = (((unsigned)b) * 512u + 2u * hp) * 256u + wp;
        ((float2*)g_cm)[q]       = make_float2(mx[0], mx[1]);
        ((float2*)g_cm)[q + 256] = make_float2(mx[2], mx[3]);
        ((float2*)g_ca)[q]       = make_float2(sm[0], sm[1]);
        ((float2*)g_ca)[q + 256] = make_float2(sm[2], sm[3]);
    }
}

// ---------------------------------------------------------------------------
// Kernel B: 7x7 SAME conv on [cm;ca] (2->32 ch), sigmoid, multiply by fs.
// Thread = 8 consecutive pixels (4 f32x2 pairs) x 4 output channels.
// Window kept as native u64 even pairs from LDS.128 (no packing movs);
// only 6 odd-parity pairs are built per row. All indices compile-time.
// Block 256 = 8 channel-groups x 32 octets; tile 64w x 4h. Grid (8,128,8).
// ---------------------------------------------------------------------------
#define THB 4

__global__ __launch_bounds__(256, 2)
void kernelB(const float* __restrict__ cow,
             const float* __restrict__ cob,
             float* __restrict__ out)
{
    __shared__ __align__(16) float s_in[2][THB + 6][72];
    __shared__ __align__(16) u64 s_wd[98][32];   // [tap][o] dup'd
    __shared__ __align__(16) u64 s_bd[32];

    const int tid = threadIdx.x;
    const int b   = blockIdx.z;
    const int tyb = blockIdx.y * THB;
    const int txb = blockIdx.x * 64;

    // weights: coalesced gmem read, dup into smem
    for (int i = tid; i < 98 * 32; i += 256) {
        int o = i / 98, tap = i - o * 98;
        float w = cow[i];
        s_wd[tap][o] = pack2(w, w);
    }
    if (tid < 32) s_bd[tid] = dup2(cob[tid]);

    // input tile with 3px halo (zero pad)
    for (int i = tid; i < 2 * (THB + 6) * 72; i += 256) {
        int plane = i / ((THB + 6) * 72);
        int rem   = i - plane * ((THB + 6) * 72);
        int r  = rem / 72;
        int cc = rem - r * 72;
        int h = tyb - 3 + r;
        int w = txb - 3 + cc;
        float v = 0.f;
        if (cc < 70 && h >= 0 && h < H_ && w >= 0 && w < W_)
            v = (plane ? g_ca : g_cm)[((unsigned)b * H_ + h) * W_ + w];
        s_in[plane][r][cc] = v;
    }
    __syncthreads();

    const int cg  = tid >> 5;       // channel group (uniform per warp)
    const int oct = tid & 31;
    const int ox  = oct & 7;        // pixel octet: cols ox*8 .. ox*8+7
    const int oy  = oct >> 3;       // row within tile

    u64 acc[4][4];  // [pixel pair][local channel]
#pragma unroll
    for (int i = 0; i < 4; i++)
#pragma unroll
        for (int c = 0; c < 4; c++) acc[i][c] = s_bd[cg * 4 + c];

#pragma unroll 1
    for (int j = 0; j < 2; j++) {
#pragma unroll 1
        for (int dy = 0; dy < 7; dy++) {
            // window floats f[0..13]; even pairs native from LDS.128/LDS.64
            const float* __restrict__ rowp = &s_in[j][oy + dy][ox * 8];
            u64 pe[7];
            {
                const ulonglong2* __restrict__ rp = (const ulonglong2*)rowp;
                ulonglong2 e01 = rp[0];   // f0f1, f2f3
                ulonglong2 e23 = rp[1];   // f4f5, f6f7
                ulonglong2 e45 = rp[2];   // f8f9, f10f11
                pe[0] = e01.x; pe[1] = e01.y;
                pe[2] = e23.x; pe[3] = e23.y;
                pe[4] = e45.x; pe[5] = e45.y;
                pe[6] = *(const u64*)(rowp + 12);   // f12f13
            }
            // odd pairs po[i] = (f[2i+1], f[2i+2]), i = 0..5
            float fl[14];
#pragma unroll
            for (int i = 0; i < 7; i++) unpack2(pe[i], fl[2*i], fl[2*i+1]);
            u64 po[6];
#pragma unroll
            for (int i = 0; i < 6; i++) po[i] = pack2(fl[2*i+1], fl[2*i+2]);

            const int tapbase = j * 49 + dy * 7;
#pragma unroll
            for (int dx = 0; dx < 7; dx++) {
                const ulonglong2* __restrict__ wp2 = (const ulonglong2*)&s_wd[tapbase + dx][cg * 4];
                ulonglong2 wa = wp2[0];
                ulonglong2 wb = wp2[1];
#pragma unroll
                for (int i = 0; i < 4; i++) {
                    u64 vv = (dx & 1) ? po[((dx - 1) >> 1) + i] : pe[(dx >> 1) + i];
                    acc[i][0] = fma2(vv, wa.x, acc[i][0]);
                    acc[i][1] = fma2(vv, wa.y, acc[i][1]);
                    acc[i][2] = fma2(vv, wb.x, acc[i][2]);
                    acc[i][3] = fma2(vv, wb.y, acc[i][3]);
                }
            }
        }
    }

    // epilogue: sigmoid(att) * fs
    const int h  = tyb + oy;
    const int w0 = txb + ox * 8;
#pragma unroll
    for (int c = 0; c < 4; c++) {
        unsigned base = (((unsigned)(b * 32 + cg * 4 + c)) * 512u + h) * 512u + w0;
#pragma unroll
        for (int i = 0; i < 4; i++) {
            float a0, a1; unpack2(acc[i][c], a0, a1);
            float2 f = *(const float2*)&g_fs[base + 2*i];
            *(float2*)&out[base + 2*i] = make_float2(fsigmoid(a0) * f.x,
                                                     fsigmoid(a1) * f.y);
        }
    }
}

extern "C" void kernel_launch(void* const* d_in, const int* in_sizes, int n_in,
                              void* d_out, int out_size)
{
    (void)in_sizes; (void)n_in; (void)out_size;
    const float* x      = (const float*)d_in[0];
    const float* mlp_w  = (const float*)d_in[1];
    const float* mlp_b  = (const float*)d_in[2];
    const float* conv_w = (const float*)d_in[3];
    const float* conv_b = (const float*)d_in[4];
    const float* cow    = (const float*)d_in[5];
    const float* cob    = (const float*)d_in[6];
    float* out = (float*)d_out;

    kernelA<<<dim3(4, 256, 8), 256>>>(x, mlp_w, mlp_b, conv_w, conv_b);
    kernelB<<<dim3(8, 128, 8), 256>>>(cow, cob, out);
}

// round 5
// speedup vs baseline: 1.0519x; 1.0519x over previous
#include <cuda_runtime.h>
#include <float.h>
#include <math.h>

#define B_ 8
#define C_ 32
#define H_ 512
#define W_ 512
#define HW_ (H_*W_)

typedef unsigned long long u64;

// Scratch (allocation-free rule: static __device__ arrays)
__device__ float g_fs[B_*C_*H_*W_];   // conv1x1 output (pre-attention)
__device__ float g_cm[B_*H_*W_];      // channel max plane
__device__ float g_ca[B_*H_*W_];      // channel mean plane

__device__ __forceinline__ float fsigmoid(float z) {
    return 1.0f / (1.0f + __expf(-z));
}

// ---- packed f32x2 helpers (sm_10x) ----
__device__ __forceinline__ u64 pack2(float lo, float hi) {
    u64 r; asm("mov.b64 %0, {%1,%2};" : "=l"(r) : "f"(lo), "f"(hi)); return r;
}
__device__ __forceinline__ u64 dup2(float v) { return pack2(v, v); }
__device__ __forceinline__ void unpack2(u64 v, float &lo, float &hi) {
    asm("mov.b64 {%0,%1}, %2;" : "=f"(lo), "=f"(hi) : "l"(v));
}
// In-place accumulate: d == c, no register-pair copy.
__device__ __forceinline__ void fma2acc(u64 &acc, u64 a, u64 b) {
    asm("fma.rn.f32x2 %0, %1, %2, %0;" : "+l"(acc) : "l"(a), "l"(b));
}
// Out-of-place (fresh destination) form.
__device__ __forceinline__ u64 fma2(u64 a, u64 b, u64 c) {
    u64 d; asm("fma.rn.f32x2 %0, %1, %2, %3;" : "=l"(d) : "l"(a), "l"(b), "l"(c)); return d;
}
__device__ __forceinline__ void add2acc(u64 &acc, u64 b) {
    asm("add.rn.f32x2 %0, %0, %1;" : "+l"(acc) : "l"(b));
}

// ---------------------------------------------------------------------------
// Kernel A: per 2x2 patch — patch max/avg -> gate -> fused (concat + 1x1 conv)
// out[o] = sum_c x[c]*(gate[c]*w1[o,c] + w2[o,c]) + b[o]
// 2 threads per patch; each owns 16 output channels.
// Accumulators are f32x2 over the horizontal pixel pair of the patch.
// Block = 256 threads = 128 patches x 2 halves. Grid = (2, 256, 8).
// ---------------------------------------------------------------------------
__global__ __launch_bounds__(256, 2)
void kernelA(const float* __restrict__ x,
             const float* __restrict__ mlp_w,
             const float* __restrict__ mlp_b,
             const float* __restrict__ conv_w,
             const float* __restrict__ conv_b)
{
    __shared__ __align__(16) u64 s_w1d[32][32];   // [c][o] = dup(conv_w[o, c])
    __shared__ __align__(16) u64 s_w2d[32][32];   // [c][o] = dup(conv_w[o, 32+c])
    __shared__ __align__(16) u64 s_bd[32];
    __shared__ float2 s_red[128][4];              // half-1 partial (mx, sum) per px

    const int tid = threadIdx.x;
    for (int i = tid; i < 1024; i += 256) {
        int o = i & 31, c = i >> 5;
        s_w1d[c][o] = dup2(conv_w[o * 64 + c]);
        s_w2d[c][o] = dup2(conv_w[o * 64 + 32 + c]);
    }
    if (tid < 32) s_bd[tid] = dup2(conv_b[tid]);
    __syncthreads();

    const int half = tid >> 7;         // 0: outputs 0-15, 1: outputs 16-31
    const int pi   = tid & 127;
    const int wp   = blockIdx.x * 128 + pi;   // patch col (float2 units)
    const int hp   = blockIdx.y;              // patch row
    const int b    = blockIdx.z;

    const u64* __restrict__ x2 = (const u64*)x;
    const float mw  = __ldg(mlp_w);
    const float mb2 = 2.0f * __ldg(mlp_b);

    u64 acc[16][2];   // [local channel][0=top row pair, 1=bottom row pair]
#pragma unroll
    for (int k = 0; k < 16; k++) { acc[k][0] = 0ull; acc[k][1] = 0ull; }

#pragma unroll 2
    for (int c = 0; c < 32; c++) {
        unsigned p = (((unsigned)(b * 32 + c)) * 512u + 2u * hp) * 256u + wp;
        u64 r0 = x2[p];          // two adjacent pixels, top row
        u64 r1 = x2[p + 256];    // two adjacent pixels, bottom row
        float r0x, r0y, r1x, r1y;
        unpack2(r0, r0x, r0y);
        unpack2(r1, r1x, r1y);
        float m = fmaxf(fmaxf(r0x, r0y), fmaxf(r1x, r1y));
        float a = 0.25f * ((r0x + r0y) + (r1x + r1y));
        float g = fsigmoid(fmaf(m + a, mw, mb2));
        u64 gg = dup2(g);
        const ulonglong2* __restrict__ w1p = (const ulonglong2*)&s_w1d[c][half * 16];
        const ulonglong2* __restrict__ w2p = (const ulonglong2*)&s_w2d[c][half * 16];
#pragma unroll
        for (int k2 = 0; k2 < 8; k2++) {
            ulonglong2 a1 = w1p[k2];
            ulonglong2 a2 = w2p[k2];
            u64 we0 = fma2(gg, a1.x, a2.x);     // dup'd effective weight
            u64 we1 = fma2(gg, a1.y, a2.y);
            fma2acc(acc[2*k2  ][0], r0, we0);
            fma2acc(acc[2*k2  ][1], r1, we0);
            fma2acc(acc[2*k2+1][0], r0, we1);
            fma2acc(acc[2*k2+1][1], r1, we1);
        }
    }

    // bias add
#pragma unroll
    for (int k = 0; k < 16; k++) {
        u64 bk = s_bd[half * 16 + k];
        add2acc(acc[k][0], bk);
        add2acc(acc[k][1], bk);
    }

    // per-pixel partial channel max/sum over this half's 16 channels
    float mx[4], sm[4];
#pragma unroll
    for (int j = 0; j < 4; j++) { mx[j] = -FLT_MAX; sm[j] = 0.f; }
#pragma unroll
    for (int k = 0; k < 16; k++) {
        float lo, hi;
        unpack2(acc[k][0], lo, hi);
        mx[0] = fmaxf(mx[0], lo); sm[0] += lo;
        mx[1] = fmaxf(mx[1], hi); sm[1] += hi;
        unpack2(acc[k][1], lo, hi);
        mx[2] = fmaxf(mx[2], lo); sm[2] += lo;
        mx[3] = fmaxf(mx[3], hi); sm[3] += hi;
    }
    if (half == 1) {
#pragma unroll
        for (int j = 0; j < 4; j++) s_red[pi][j] = make_float2(mx[j], sm[j]);
    }

    // fs stores: u64 = adjacent pixel pair, coalesced within warp
    u64* __restrict__ fs2 = (u64*)g_fs;
#pragma unroll
    for (int k = 0; k < 16; k++) {
        int o = half * 16 + k;
        unsigned p = (((unsigned)(b * 32 + o)) * 512u + 2u * hp) * 256u + wp;
        fs2[p]       = acc[k][0];
        fs2[p + 256] = acc[k][1];
    }

    __syncthreads();
    if (half == 0) {
#pragma unroll
        for (int j = 0; j < 4; j++) {
            float2 r = s_red[pi][j];
            mx[j] = fmaxf(mx[j], r.x);
            sm[j] = (sm[j] + r.y) * (1.0f / 32.0f);
        }
        unsigned q = (((unsigned)b) * 512u + 2u * hp) * 256u + wp;
        ((float2*)g_cm)[q]       = make_float2(mx[0], mx[1]);
        ((float2*)g_cm)[q + 256] = make_float2(mx[2], mx[3]);
        ((float2*)g_ca)[q]       = make_float2(sm[0], sm[1]);
        ((float2*)g_ca)[q + 256] = make_float2(sm[2], sm[3]);
    }
}

// ---------------------------------------------------------------------------
// Kernel B: 7x7 SAME conv on [cm;ca] (2->32 ch), sigmoid, multiply by fs.
// Thread = 8 consecutive pixels (4 f32x2 pairs) x 4 output channels.
// Window kept as native u64 even pairs from LDS.128; 6 odd-parity pairs
// built per row. In-place FMA2 accumulation (no register-pair copies).
// Block 256 = 8 channel-groups x 32 octets; tile 64w x 4h. Grid (8,128,8).
// ---------------------------------------------------------------------------
#define THB 4

__global__ __launch_bounds__(256, 2)
void kernelB(const float* __restrict__ cow,
             const float* __restrict__ cob,
             float* __restrict__ out)
{
    __shared__ __align__(16) float s_in[2][THB + 6][72];
    __shared__ __align__(16) u64 s_wd[98][32];   // [tap][o] dup'd
    __shared__ __align__(16) u64 s_bd[32];

    const int tid = threadIdx.x;
    const int b   = blockIdx.z;
    const int tyb = blockIdx.y * THB;
    const int txb = blockIdx.x * 64;

    // weights: coalesced gmem read, dup into smem
    for (int i = tid; i < 98 * 32; i += 256) {
        int o = i / 98, tap = i - o * 98;
        float w = cow[i];
        s_wd[tap][o] = pack2(w, w);
    }
    if (tid < 32) s_bd[tid] = dup2(cob[tid]);

    // input tile with 3px halo (zero pad)
    for (int i = tid; i < 2 * (THB + 6) * 72; i += 256) {
        int plane = i / ((THB + 6) * 72);
        int rem   = i - plane * ((THB + 6) * 72);
        int r  = rem / 72;
        int cc = rem - r * 72;
        int h = tyb - 3 + r;
        int w = txb - 3 + cc;
        float v = 0.f;
        if (cc < 70 && h >= 0 && h < H_ && w >= 0 && w < W_)
            v = (plane ? g_ca : g_cm)[((unsigned)b * H_ + h) * W_ + w];
        s_in[plane][r][cc] = v;
    }
    __syncthreads();

    const int cg  = tid >> 5;       // channel group (uniform per warp)
    const int oct = tid & 31;
    const int ox  = oct & 7;        // pixel octet: cols ox*8 .. ox*8+7
    const int oy  = oct >> 3;       // row within tile

    u64 acc[4][4];  // [pixel pair][local channel]
#pragma unroll
    for (int i = 0; i < 4; i++)
#pragma unroll
        for (int c = 0; c < 4; c++) acc[i][c] = s_bd[cg * 4 + c];

#pragma unroll 1
    for (int j = 0; j < 2; j++) {
#pragma unroll 1
        for (int dy = 0; dy < 7; dy++) {
            // window floats f[0..13]; even pairs native from LDS.128/LDS.64
            const float* __restrict__ rowp = &s_in[j][oy + dy][ox * 8];
            u64 pe[7];
            {
                const ulonglong2* __restrict__ rp = (const ulonglong2*)rowp;
                ulonglong2 e01 = rp[0];   // f0f1, f2f3
                ulonglong2 e23 = rp[1];   // f4f5, f6f7
                ulonglong2 e45 = rp[2];   // f8f9, f10f11
                pe[0] = e01.x; pe[1] = e01.y;
                pe[2] = e23.x; pe[3] = e23.y;
                pe[4] = e45.x; pe[5] = e45.y;
                pe[6] = *(const u64*)(rowp + 12);   // f12f13
            }
            // odd pairs po[i] = (f[2i+1], f[2i+2]), i = 0..5
            float fl[14];
#pragma unroll
            for (int i = 0; i < 7; i++) unpack2(pe[i], fl[2*i], fl[2*i+1]);
            u64 po[6];
#pragma unroll
            for (int i = 0; i < 6; i++) po[i] = pack2(fl[2*i+1], fl[2*i+2]);

            const int tapbase = j * 49 + dy * 7;
#pragma unroll
            for (int dx = 0; dx < 7; dx++) {
                const ulonglong2* __restrict__ wp2 = (const ulonglong2*)&s_wd[tapbase + dx][cg * 4];
                ulonglong2 wa = wp2[0];
                ulonglong2 wb = wp2[1];
#pragma unroll
                for (int i = 0; i < 4; i++) {
                    u64 vv = (dx & 1) ? po[((dx - 1) >> 1) + i] : pe[(dx >> 1) + i];
                    fma2acc(acc[i][0], vv, wa.x);
                    fma2acc(acc[i][1], vv, wa.y);
                    fma2acc(acc[i][2], vv, wb.x);
                    fma2acc(acc[i][3], vv, wb.y);
                }
            }
        }
    }

    // epilogue: sigmoid(att) * fs
    const int h  = tyb + oy;
    const int w0 = txb + ox * 8;
#pragma unroll
    for (int c = 0; c < 4; c++) {
        unsigned base = (((unsigned)(b * 32 + cg * 4 + c)) * 512u + h) * 512u + w0;
#pragma unroll
        for (int i = 0; i < 4; i++) {
            float a0, a1; unpack2(acc[i][c], a0, a1);
            float2 f = *(const float2*)&g_fs[base + 2*i];
            *(float2*)&out[base + 2*i] = make_float2(fsigmoid(a0) * f.x,
                                                     fsigmoid(a1) * f.y);
        }
    }
}

extern "C" void kernel_launch(void* const* d_in, const int* in_sizes, int n_in,
                              void* d_out, int out_size)
{
    (void)in_sizes; (void)n_in; (void)out_size;
    const float* x      = (const float*)d_in[0];
    const float* mlp_w  = (const float*)d_in[1];
    const float* mlp_b  = (const float*)d_in[2];
    const float* conv_w = (const float*)d_in[3];
    const float* conv_b = (const float*)d_in[4];
    const float* cow    = (const float*)d_in[5];
    const float* cob    = (const float*)d_in[6];
    float* out = (float*)d_out;

    kernelA<<<dim3(2, 256, 8), 256>>>(x, mlp_w, mlp_b, conv_w, conv_b);
    kernelB<<<dim3(8, 128, 8), 256>>>(cow, cob, out);
}

// round 6
// speedup vs baseline: 1.1038x; 1.0494x over previous
#include <cuda_runtime.h>
#include <float.h>
#include <math.h>

#define B_ 8
#define C_ 32
#define H_ 512
#define W_ 512
#define HW_ (H_*W_)

typedef unsigned long long u64;

// Scratch (allocation-free rule: static __device__ arrays)
__device__ float g_fs[B_*C_*H_*W_];   // conv1x1 output (pre-attention)
__device__ float g_cm[B_*H_*W_];      // channel max plane
__device__ float g_ca[B_*H_*W_];      // channel mean plane

__device__ __forceinline__ float fsigmoid(float z) {
    return 1.0f / (1.0f + __expf(-z));
}

// ---- packed f32x2 helpers (sm_10x) ----
__device__ __forceinline__ u64 pack2(float lo, float hi) {
    u64 r; asm("mov.b64 %0, {%1,%2};" : "=l"(r) : "f"(lo), "f"(hi)); return r;
}
__device__ __forceinline__ u64 dup2(float v) { return pack2(v, v); }
__device__ __forceinline__ void unpack2(u64 v, float &lo, float &hi) {
    asm("mov.b64 {%0,%1}, %2;" : "=f"(lo), "=f"(hi) : "l"(v));
}
__device__ __forceinline__ void fma2acc(u64 &acc, u64 a, u64 b) {
    asm("fma.rn.f32x2 %0, %1, %2, %0;" : "+l"(acc) : "l"(a), "l"(b));
}
__device__ __forceinline__ u64 fma2(u64 a, u64 b, u64 c) {
    u64 d; asm("fma.rn.f32x2 %0, %1, %2, %3;" : "=l"(d) : "l"(a), "l"(b), "l"(c)); return d;
}
__device__ __forceinline__ void add2acc(u64 &acc, u64 b) {
    asm("add.rn.f32x2 %0, %0, %1;" : "+l"(acc) : "l"(b));
}

// ---------------------------------------------------------------------------
// Kernel A: per 2x2 patch — patch max/avg -> gate -> fused (concat + 1x1 conv)
// 2 threads per patch; each owns 16 output channels. f32x2 pixel-pair accums.
// Block = 256 threads = 128 patches x 2 halves. Grid = (2, 256, 8).
// ---------------------------------------------------------------------------
__global__ __launch_bounds__(256, 2)
void kernelA(const float* __restrict__ x,
             const float* __restrict__ mlp_w,
             const float* __restrict__ mlp_b,
             const float* __restrict__ conv_w,
             const float* __restrict__ conv_b)
{
    __shared__ __align__(16) u64 s_w1d[32][32];   // [c][o] = dup(conv_w[o, c])
    __shared__ __align__(16) u64 s_w2d[32][32];   // [c][o] = dup(conv_w[o, 32+c])
    __shared__ __align__(16) u64 s_bd[32];
    __shared__ float2 s_red[128][4];              // half-1 partial (mx, sum) per px

    const int tid = threadIdx.x;
    for (int i = tid; i < 1024; i += 256) {
        int o = i & 31, c = i >> 5;
        s_w1d[c][o] = dup2(conv_w[o * 64 + c]);
        s_w2d[c][o] = dup2(conv_w[o * 64 + 32 + c]);
    }
    if (tid < 32) s_bd[tid] = dup2(conv_b[tid]);
    __syncthreads();

    const int half = tid >> 7;         // 0: outputs 0-15, 1: outputs 16-31
    const int pi   = tid & 127;
    const int wp   = blockIdx.x * 128 + pi;   // patch col (float2 units)
    const int hp   = blockIdx.y;              // patch row
    const int b    = blockIdx.z;

    const u64* __restrict__ x2 = (const u64*)x;
    const float mw  = __ldg(mlp_w);
    const float mb2 = 2.0f * __ldg(mlp_b);

    u64 acc[16][2];   // [local channel][0=top row pair, 1=bottom row pair]
#pragma unroll
    for (int k = 0; k < 16; k++) { acc[k][0] = 0ull; acc[k][1] = 0ull; }

#pragma unroll 4
    for (int c = 0; c < 32; c++) {
        unsigned p = (((unsigned)(b * 32 + c)) * 512u + 2u * hp) * 256u + wp;
        u64 r0 = x2[p];          // two adjacent pixels, top row
        u64 r1 = x2[p + 256];    // two adjacent pixels, bottom row
        float r0x, r0y, r1x, r1y;
        unpack2(r0, r0x, r0y);
        unpack2(r1, r1x, r1y);
        float m = fmaxf(fmaxf(r0x, r0y), fmaxf(r1x, r1y));
        float a = 0.25f * ((r0x + r0y) + (r1x + r1y));
        float g = fsigmoid(fmaf(m + a, mw, mb2));
        u64 gg = dup2(g);
        const ulonglong2* __restrict__ w1p = (const ulonglong2*)&s_w1d[c][half * 16];
        const ulonglong2* __restrict__ w2p = (const ulonglong2*)&s_w2d[c][half * 16];
#pragma unroll
        for (int k2 = 0; k2 < 8; k2++) {
            ulonglong2 a1 = w1p[k2];
            ulonglong2 a2 = w2p[k2];
            u64 we0 = fma2(gg, a1.x, a2.x);     // dup'd effective weight
            u64 we1 = fma2(gg, a1.y, a2.y);
            fma2acc(acc[2*k2  ][0], r0, we0);
            fma2acc(acc[2*k2  ][1], r1, we0);
            fma2acc(acc[2*k2+1][0], r0, we1);
            fma2acc(acc[2*k2+1][1], r1, we1);
        }
    }

    // bias add
#pragma unroll
    for (int k = 0; k < 16; k++) {
        u64 bk = s_bd[half * 16 + k];
        add2acc(acc[k][0], bk);
        add2acc(acc[k][1], bk);
    }

    // per-pixel partial channel max/sum over this half's 16 channels
    float mx[4], sm[4];
#pragma unroll
    for (int j = 0; j < 4; j++) { mx[j] = -FLT_MAX; sm[j] = 0.f; }
#pragma unroll
    for (int k = 0; k < 16; k++) {
        float lo, hi;
        unpack2(acc[k][0], lo, hi);
        mx[0] = fmaxf(mx[0], lo); sm[0] += lo;
        mx[1] = fmaxf(mx[1], hi); sm[1] += hi;
        unpack2(acc[k][1], lo, hi);
        mx[2] = fmaxf(mx[2], lo); sm[2] += lo;
        mx[3] = fmaxf(mx[3], hi); sm[3] += hi;
    }
    if (half == 1) {
#pragma unroll
        for (int j = 0; j < 4; j++) s_red[pi][j] = make_float2(mx[j], sm[j]);
    }

    // fs stores: u64 = adjacent pixel pair, coalesced within warp
    u64* __restrict__ fs2 = (u64*)g_fs;
#pragma unroll
    for (int k = 0; k < 16; k++) {
        int o = half * 16 + k;
        unsigned p = (((unsigned)(b * 32 + o)) * 512u + 2u * hp) * 256u + wp;
        fs2[p]       = acc[k][0];
        fs2[p + 256] = acc[k][1];
    }

    __syncthreads();
    if (half == 0) {
#pragma unroll
        for (int j = 0; j < 4; j++) {
            float2 r = s_red[pi][j];
            mx[j] = fmaxf(mx[j], r.x);
            sm[j] = (sm[j] + r.y) * (1.0f / 32.0f);
        }
        unsigned q = (((unsigned)b) * 512u + 2u * hp) * 256u + wp;
        ((float2*)g_cm)[q]       = make_float2(mx[0], mx[1]);
        ((float2*)g_cm)[q + 256] = make_float2(mx[2], mx[3]);
        ((float2*)g_ca)[q]       = make_float2(sm[0], sm[1]);
        ((float2*)g_ca)[q + 256] = make_float2(sm[2], sm[3]);
    }
}

// ---------------------------------------------------------------------------
// Kernel B: 7x7 SAME conv on [cm;ca] (2->32 ch), sigmoid, multiply by fs.
// Thread = 8 consecutive pixels (4 f32x2 pairs) x 4 output channels.
// Input tile stored TWICE in smem: natural + shifted-by-1-float, so both
// pixel-pair parities load as native u64 vectors. ZERO pack/unpack in loop.
// Block 256 = 8 channel-groups x 32 octets; tile 64w x 4h. Grid (8,128,8).
// ---------------------------------------------------------------------------
#define THB 4

__global__ __launch_bounds__(256, 3)
void kernelB(const float* __restrict__ cow,
             const float* __restrict__ cob,
             float* __restrict__ out)
{
    __shared__ __align__(16) float s_e[2][THB + 6][72];  // natural
    __shared__ __align__(16) float s_o[2][THB + 6][72];  // shifted: s_o[c] = in[c+1]
    __shared__ __align__(16) u64 s_wd[98][32];   // [tap][o] dup'd
    __shared__ __align__(16) u64 s_bd[32];

    const int tid = threadIdx.x;
    const int b   = blockIdx.z;
    const int tyb = blockIdx.y * THB;
    const int txb = blockIdx.x * 64;

    // weights: coalesced gmem read, dup into smem
    for (int i = tid; i < 98 * 32; i += 256) {
        int o = i / 98, tap = i - o * 98;
        float w = cow[i];
        s_wd[tap][o] = pack2(w, w);
    }
    if (tid < 32) s_bd[tid] = dup2(cob[tid]);

    // input tile with 3px halo (zero pad); dual store (natural + shifted)
    for (int i = tid; i < 2 * (THB + 6) * 72; i += 256) {
        int plane = i / ((THB + 6) * 72);
        int rem   = i - plane * ((THB + 6) * 72);
        int r  = rem / 72;
        int cc = rem - r * 72;
        int h = tyb - 3 + r;
        int w = txb - 3 + cc;
        float v = 0.f;
        if (cc < 70 && h >= 0 && h < H_ && w >= 0 && w < W_)
            v = (plane ? g_ca : g_cm)[((unsigned)b * H_ + h) * W_ + w];
        s_e[plane][r][cc] = v;
        if (cc >= 1) s_o[plane][r][cc - 1] = v;
        if (cc == 71) s_o[plane][r][71] = 0.f;
    }
    __syncthreads();

    const int cg  = tid >> 5;       // channel group (uniform per warp)
    const int oct = tid & 31;
    const int ox  = oct & 7;        // pixel octet: cols ox*8 .. ox*8+7
    const int oy  = oct >> 3;       // row within tile

    u64 acc[4][4];  // [pixel pair][local channel]
#pragma unroll
    for (int i = 0; i < 4; i++)
#pragma unroll
        for (int c = 0; c < 4; c++) acc[i][c] = s_bd[cg * 4 + c];

#pragma unroll 1
    for (int j = 0; j < 2; j++) {
#pragma unroll 1
        for (int dy = 0; dy < 7; dy++) {
            // even pairs pe[i] = (f[2i], f[2i+1]); odd pairs po[i] = (f[2i+1], f[2i+2])
            // both native u64 loads (no movs)
            const float* __restrict__ rowe = &s_e[j][oy + dy][ox * 8];
            const float* __restrict__ rowo = &s_o[j][oy + dy][ox * 8];
            u64 pe[7], po[6];
            {
                const ulonglong2* __restrict__ rp = (const ulonglong2*)rowe;
                ulonglong2 e01 = rp[0], e23 = rp[1], e45 = rp[2];
                pe[0] = e01.x; pe[1] = e01.y;
                pe[2] = e23.x; pe[3] = e23.y;
                pe[4] = e45.x; pe[5] = e45.y;
                pe[6] = *(const u64*)(rowe + 12);
                const ulonglong2* __restrict__ op = (const ulonglong2*)rowo;
                ulonglong2 o01 = op[0], o23 = op[1];
                po[0] = o01.x; po[1] = o01.y;
                po[2] = o23.x; po[3] = o23.y;
                po[4] = *(const u64*)(rowo + 8);
                po[5] = *(const u64*)(rowo + 10);
            }

            const int tapbase = j * 49 + dy * 7;
#pragma unroll
            for (int dx = 0; dx < 7; dx++) {
                const ulonglong2* __restrict__ wp2 = (const ulonglong2*)&s_wd[tapbase + dx][cg * 4];
                ulonglong2 wa = wp2[0];
                ulonglong2 wb = wp2[1];
#pragma unroll
                for (int i = 0; i < 4; i++) {
                    u64 vv = (dx & 1) ? po[((dx - 1) >> 1) + i] : pe[(dx >> 1) + i];
                    fma2acc(acc[i][0], vv, wa.x);
                    fma2acc(acc[i][1], vv, wa.y);
                    fma2acc(acc[i][2], vv, wb.x);
                    fma2acc(acc[i][3], vv, wb.y);
                }
            }
        }
    }

    // epilogue: sigmoid(att) * fs
    const int h  = tyb + oy;
    const int w0 = txb + ox * 8;
#pragma unroll
    for (int c = 0; c < 4; c++) {
        unsigned base = (((unsigned)(b * 32 + cg * 4 + c)) * 512u + h) * 512u + w0;
#pragma unroll
        for (int i = 0; i < 4; i++) {
            float a0, a1; unpack2(acc[i][c], a0, a1);
            float2 f = *(const float2*)&g_fs[base + 2*i];
            *(float2*)&out[base + 2*i] = make_float2(fsigmoid(a0) * f.x,
                                                     fsigmoid(a1) * f.y);
        }
    }
}

extern "C" void kernel_launch(void* const* d_in, const int* in_sizes, int n_in,
                              void* d_out, int out_size)
{
    (void)in_sizes; (void)n_in; (void)out_size;
    const float* x      = (const float*)d_in[0];
    const float* mlp_w  = (const float*)d_in[1];
    const float* mlp_b  = (const float*)d_in[2];
    const float* conv_w = (const float*)d_in[3];
    const float* conv_b = (const float*)d_in[4];
    const float* cow    = (const float*)d_in[5];
    const float* cob    = (const float*)d_in[6];
    float* out = (float*)d_out;

    kernelA<<<dim3(2, 256, 8), 256>>>(x, mlp_w, mlp_b, conv_w, conv_b);
    kernelB<<<dim3(8, 128, 8), 256>>>(cow, cob, out);
}